// round 13
// baseline (speedup 1.0000x reference)
#include <cuda_runtime.h>
#include <cuda_bf16.h>
#include <cuda_fp8.h>
#include <cstdint>

static constexpr int KP = 1664;    // K padded stride (fc1 iterates only 1600)

// ---------------- scratch (device globals; no allocation) ----------------
// g_absmax is zero-initialized at module load and ONLY written via atomicMax
// with deterministic values -> idempotent across graph replays.
__device__ unsigned g_absmax[4];                                   // w1,w2,wl1,wl2 abs-max bits
__device__ __align__(256) unsigned char g_qwl1f8[4096 * KP];       // wl1 int codes, e4m3, padded K
__device__ __align__(256) __nv_bfloat16 g_qw2p[4 * 64 * 88];       // w2 codes, padded [c][oc][88]
__device__ __align__(256) __nv_bfloat16 g_qwl2[10 * 4096];         // wl2 int codes, bf16
__device__ __align__(256) unsigned char g_a2f8[1024 * KP];         // conv2 out codes, e4m3, padded K
__device__ __align__(256) __nv_bfloat16 g_a3[1024 * 4096];         // fc1 out codes 0..15
__device__ short g_srcIdx[128 * 80];                               // conv2 im2col gather index
__device__ short g_dstIdx[128 * 80];                               // conv2 im2col smem dest

// ---------------- helpers ----------------
__device__ __forceinline__ void warp_max_atomic(float m, int slot) {
#pragma unroll
    for (int o = 16; o > 0; o >>= 1)
        m = fmaxf(m, __shfl_xor_sync(0xffffffffu, m, o));
    if ((threadIdx.x & 31) == 0)
        atomicMax(&g_absmax[slot], __float_as_uint(m));
}

__device__ __forceinline__ float f4max(float4 v) {
    return fmaxf(fmaxf(fabsf(v.x), fabsf(v.y)), fmaxf(fabsf(v.z), fabsf(v.w)));
}

__device__ __forceinline__ float qclip7(float v, float inv_s) {
    float k = rintf(v * inv_s);
    return fminf(fmaxf(k, -7.f), 7.f);
}

__device__ __forceinline__ unsigned short cvt_e4m3x2(float lo, float hi) {
    unsigned short r;
    asm("cvt.rn.satfinite.e4m3x2.f32 %0, %1, %2;" : "=h"(r) : "f"(hi), "f"(lo));
    return r;
}

// ---------------- prep1: all absmax reductions + im2col tables (one launch) ---------------
__global__ void prep1_kernel(const float4* __restrict__ wl1,
                             const float4* __restrict__ w1,
                             const float4* __restrict__ w2,
                             const float4* __restrict__ wl2) {
    const int t = threadIdx.x;
    const unsigned bid = blockIdx.x;
    if (bid < 800) {                         // wl1: 1638400 float4, 8 loads/thread
        const int base = bid * 256 + t;
        const int stride = 800 * 256;
        float4 v[8];
#pragma unroll
        for (int j = 0; j < 8; j++) v[j] = wl1[base + j * stride];
        float m = 0.f;
#pragma unroll
        for (int j = 0; j < 8; j++) m = fmaxf(m, f4max(v[j]));
        warp_max_atomic(m, 2);
    } else if (bid < 859) {
        const int sb = bid - 800;
        float m = 0.f;
        if (sb == 0) {                       // w1: 72 float4
            if (t < 72) m = f4max(w1[t]);
            warp_max_atomic(m, 0);
        } else if (sb <= 18) {               // w2: 4608 float4
            const int i = (sb - 1) * 256 + t;
            if (i < 4608) m = f4max(w2[i]);
            warp_max_atomic(m, 1);
        } else {                             // wl2: 10240 float4
            const int i = (sb - 19) * 256 + t;
            if (i < 10240) m = f4max(wl2[i]);
            warp_max_atomic(m, 3);
        }
    } else {                                 // im2col tables: 10240 entries
        const int idx = (bid - 859) * 256 + t;
        if (idx < 128 * 80) {
            const int r = idx / 80, col = idx % 80;
            short s = -1;
            if (r < 121 && col < 72) {
                const int icl = col / 9, kk = col % 9;
                const int ky = kk / 3, kx = kk % 3;
                const int oy = r / 11, ox = r % 11;
                s = (short)(icl * 169 + (oy + ky) * 13 + ox + kx);
            }
            g_srcIdx[idx] = s;
            g_dstIdx[idx] = (short)(r * 88 + col);
        }
    }
}

// ---------------- prep2: all weight quantization (one launch) ----------------
__global__ void prep2_kernel(const float4* __restrict__ wl1,
                             const float* __restrict__ w2,
                             const float* __restrict__ wl2) {
    const int t = threadIdx.x;
    const unsigned bid = blockIdx.x;
    if (bid < 1600) {
        const float inv_s = 7.f / __uint_as_float(g_absmax[2]);
        const int i = bid * 256 + t;          // 0 .. 409599, 16 elems/thread
        unsigned short h[8];
#pragma unroll
        for (int q = 0; q < 4; q++) {
            float4 a = wl1[4 * i + q];
            h[2 * q + 0] = cvt_e4m3x2(qclip7(a.x, inv_s), qclip7(a.y, inv_s));
            h[2 * q + 1] = cvt_e4m3x2(qclip7(a.z, inv_s), qclip7(a.w, inv_s));
        }
        const int row = i / 100, c16 = i % 100;    // 1600/16 = 100 granules per row
        *(uint4*)&g_qwl1f8[(size_t)row * KP + c16 * 16] = *(const uint4*)h;
    } else if (bid < 1688) {                  // g_qw2p: 22528 entries
        const int idx = (bid - 1600) * 256 + t;
        if (idx < 22528) {
            const int c = idx / 5632, rem = idx % 5632;
            const int oc = rem / 88, col = rem % 88;
            float v = 0.f;
            if (col < 72) {
                const float inv_s = 7.f / __uint_as_float(g_absmax[1]);
                v = qclip7(w2[oc * 288 + c * 72 + col], inv_s);
            }
            g_qw2p[idx] = __float2bfloat16(v);
        }
    } else {                                  // wl2: 40960 entries
        const int i = (bid - 1688) * 256 + t;
        const float inv_s = 7.f / __uint_as_float(g_absmax[3]);
        g_qwl2[i] = __float2bfloat16(qclip7(wl2[i], inv_s));
    }
}

// ---------------- fused conv: conv1 -> pool -> fq -> conv2 (MMA) -> pool -> fq ----------------
static constexpr int C2_RS = 88;
static constexpr int SI_OFF = 0;
static constexpr int SA_OFF = 10880;
static constexpr int SB_OFF = 33408;
static constexpr int SO_OFF = 0;

__global__ __launch_bounds__(256) void conv_fused_kernel(const float* __restrict__ x,
                                                         const float* __restrict__ w1,
                                                         const float* __restrict__ ps_in,
                                                         const float* __restrict__ ps_a1,
                                                         const float* __restrict__ ps_a2) {
    __shared__ __align__(16) unsigned char smraw[44672];
    __nv_bfloat16* si = (__nv_bfloat16*)(smraw + SI_OFF);
    __nv_bfloat16* sA = (__nv_bfloat16*)(smraw + SA_OFF);
    __nv_bfloat16* sB = (__nv_bfloat16*)(smraw + SB_OFF);

    const int b = blockIdx.x;
    const int t = threadIdx.x;
    const int lane = t & 31, warp = t >> 5;
    const int wm = (warp >> 1) * 32;
    const int wn = (warp & 1) * 32;

    const float s_in = *ps_in;
    const float inv_s_in = 1.f / s_in;

    // ===== conv1 phase =====
    {
        float* sx = (float*)(smraw + SA_OFF);
        float* sw = (float*)(smraw + SA_OFF + 3200);
        const float s_a1 = *ps_a1;
        const float inv_s_a1 = 1.f / s_a1;
        const float inv_w1 = 7.f / __uint_as_float(g_absmax[0]);

        const float* xb = x + b * 784;
        for (int i = t; i < 784; i += 256) {
            float q = rintf(xb[i] * inv_s_in);
            sx[i] = fminf(fmaxf(q, -8.f), 7.f);
        }
        for (int i = t; i < 288; i += 256)
            sw[i] = qclip7(w1[i], inv_w1);
        __syncthreads();

        const float oscale = s_in * (__uint_as_float(g_absmax[0]) / 7.f);
        for (int o = t; o < 32 * 169; o += 256) {
            const int c = o / 169;
            const int r = o % 169;
            const int pi = r / 13, pj = r % 13;
            const float* wk = sw + c * 9;
            float m = 0.f;
#pragma unroll
            for (int dy = 0; dy < 2; dy++) {
#pragma unroll
                for (int dx = 0; dx < 2; dx++) {
                    const int r0 = 2 * pi + dy, c0 = 2 * pj + dx;
                    float acc = 0.f;
#pragma unroll
                    for (int ky = 0; ky < 3; ky++)
#pragma unroll
                        for (int kx = 0; kx < 3; kx++)
                            acc += sx[(r0 + ky) * 28 + (c0 + kx)] * wk[ky * 3 + kx];
                    const float y = acc * oscale;
                    const float mm = (y > 0.f) ? fminf(rintf(y * inv_s_a1), 15.f) : 0.f;
                    m = fmaxf(m, mm);
                }
            }
            float k = rintf(m * s_a1 * inv_s_in);
            k = fminf(fmaxf(k, -8.f), 7.f);
            si[o] = __float2bfloat16(k);
        }
    }

    // ===== conv2 phase =====
    float acc[2][4][4];
#pragma unroll
    for (int mi = 0; mi < 2; mi++)
#pragma unroll
        for (int ni = 0; ni < 4; ni++)
#pragma unroll
            for (int q = 0; q < 4; q++) acc[mi][ni][q] = 0.f;

    const __nv_bfloat16 zero = __float2bfloat16(0.f);

    for (int c = 0; c < 4; ++c) {
        __syncthreads();
        {
            const int base = c * 1352;
#pragma unroll 8
            for (int i = 0; i < 40; i++) {
                const int idx = t + 256 * i;
                const short s = g_srcIdx[idx];
                const short d = g_dstIdx[idx];
                sA[d] = (s >= 0) ? si[base + s] : zero;
            }
        }
        {
            const uint4* src = (const uint4*)(g_qw2p + c * 5632);
            uint4* dst = (uint4*)sB;
#pragma unroll
            for (int i = t; i < 704; i += 256) dst[i] = src[i];
        }
        __syncthreads();

#pragma unroll
        for (int ks = 0; ks < 5; ++ks) {
            const int k0 = ks * 16;
            unsigned af[2][4], bf[4][2];
#pragma unroll
            for (int mi = 0; mi < 2; mi++) {
                const int row = wm + mi * 16 + (lane & 15);
                const int g = (k0 >> 3) + (lane >> 4);
                unsigned addr = (unsigned)__cvta_generic_to_shared(sA + row * C2_RS + g * 8);
                asm volatile("ldmatrix.sync.aligned.m8n8.x4.shared.b16 {%0,%1,%2,%3}, [%4];"
                             : "=r"(af[mi][0]), "=r"(af[mi][1]), "=r"(af[mi][2]), "=r"(af[mi][3])
                             : "r"(addr));
            }
#pragma unroll
            for (int ni = 0; ni < 4; ni++) {
                const int row = wn + ni * 8 + (lane & 7);
                const int g = (k0 >> 3) + ((lane >> 3) & 1);
                unsigned addr = (unsigned)__cvta_generic_to_shared(sB + row * C2_RS + g * 8);
                asm volatile("ldmatrix.sync.aligned.m8n8.x2.shared.b16 {%0,%1}, [%2];"
                             : "=r"(bf[ni][0]), "=r"(bf[ni][1])
                             : "r"(addr));
            }
#pragma unroll
            for (int mi = 0; mi < 2; mi++)
#pragma unroll
                for (int ni = 0; ni < 4; ni++)
                    asm volatile(
                        "mma.sync.aligned.m16n8k16.row.col.f32.bf16.bf16.f32 "
                        "{%0,%1,%2,%3}, {%4,%5,%6,%7}, {%8,%9}, {%0,%1,%2,%3};"
                        : "+f"(acc[mi][ni][0]), "+f"(acc[mi][ni][1]),
                          "+f"(acc[mi][ni][2]), "+f"(acc[mi][ni][3])
                        : "r"(af[mi][0]), "r"(af[mi][1]), "r"(af[mi][2]), "r"(af[mi][3]),
                          "r"(bf[ni][0]), "r"(bf[ni][1]));
        }
    }
    __syncthreads();

    float* sO = (float*)(smraw + SO_OFF);
    {
        const int rg = lane >> 2, cg = (lane & 3) * 2;
#pragma unroll
        for (int mi = 0; mi < 2; mi++)
#pragma unroll
            for (int ni = 0; ni < 4; ni++) {
                const int r0 = wm + mi * 16 + rg;
                const int cc = wn + ni * 8 + cg;
                *(float2*)&sO[r0 * 64 + cc] = make_float2(acc[mi][ni][0], acc[mi][ni][1]);
                *(float2*)&sO[(r0 + 8) * 64 + cc] = make_float2(acc[mi][ni][2], acc[mi][ni][3]);
            }
    }
    __syncthreads();

    const float s_a2 = *ps_a2;
    const float inv_s_a2 = 1.f / s_a2;
    const float osc = s_in * (__uint_as_float(g_absmax[1]) / 7.f);
    if (t < 200) {
        const int sp = t % 25, g = t / 25;
        const int ph = sp / 5, pw = sp % 5;
#pragma unroll
        for (int j = 0; j < 8; j++) {
            const int oc = g * 8 + j;
            float m = 0.f;
#pragma unroll
            for (int dy = 0; dy < 2; dy++)
#pragma unroll
                for (int dx = 0; dx < 2; dx++) {
                    const int pos = (2 * ph + dy) * 11 + (2 * pw + dx);
                    const float y = sO[pos * 64 + oc] * osc;
                    const float mm = (y > 0.f) ? fminf(rintf(y * inv_s_a2), 15.f) : 0.f;
                    m = fmaxf(m, mm);
                }
            float k = rintf(m * s_a2 * inv_s_in);
            k = fminf(fmaxf(k, -8.f), 7.f);
            g_a2f8[(size_t)b * KP + oc * 25 + ph * 5 + pw] =
                __nv_cvt_float_to_fp8(k, __NV_SATFINITE, __NV_E4M3);
        }
    }
}

// ---------------- fc1: FP8 e4m3 m16n8k32, tile 128x64, 3 blocks/SM ----------------
__global__ __launch_bounds__(256, 3) void fc1_kernel(const float* __restrict__ ps_in,
                                                     const float* __restrict__ ps_a3) {
    __shared__ __align__(16) unsigned char As[2 * 128 * 32];   // 8 KB
    __shared__ __align__(16) unsigned char Bs[2 * 64 * 32];    // 4 KB
    const int t = threadIdx.x;
    const int lane = t & 31, warp = t >> 5;
    const int wm = (warp >> 1) * 32;    // 4 warps in M (32 rows each)
    const int wn = (warp & 1) * 32;     // 2 warps in N (32 cols each)
    const int bm = blockIdx.y * 128, bn = blockIdx.x * 64;

    const unsigned char* Ag = g_a2f8;
    const unsigned char* Bg = g_qwl1f8;

    // A loader: 256 granules (128 rows x 2); B loader: 128 granules (64 rows x 2)
    const int lrA = t >> 1;
    const int gq = t & 1;
    const int sofsA = lrA * 32 + (gq ^ ((lrA >> 2) & 1)) * 16;
    const int lrB = lrA & 63;           // rows 0..63 for t<128
    const int sofsB = lrB * 32 + (gq ^ ((lrB >> 2) & 1)) * 16;

    float acc[2][4][4];
#pragma unroll
    for (int mi = 0; mi < 2; mi++)
#pragma unroll
        for (int ni = 0; ni < 4; ni++)
#pragma unroll
            for (int q = 0; q < 4; q++) acc[mi][ni][q] = 0.f;

    uint4 ra, rb;
    ra = *(const uint4*)(Ag + (size_t)(bm + lrA) * KP + gq * 16);
    if (t < 128) rb = *(const uint4*)(Bg + (size_t)(bn + lrB) * KP + gq * 16);
    *(uint4*)&As[sofsA] = ra;
    if (t < 128) *(uint4*)&Bs[sofsB] = rb;
    __syncthreads();

    for (int kt = 0; kt < 50; ++kt) {
        const int cur = kt & 1;
        if (kt < 49) {
            const int k0 = (kt + 1) * 32;
            ra = *(const uint4*)(Ag + (size_t)(bm + lrA) * KP + k0 + gq * 16);
            if (t < 128) rb = *(const uint4*)(Bg + (size_t)(bn + lrB) * KP + k0 + gq * 16);
        }
        const unsigned char* Ab = As + cur * 4096;
        const unsigned char* Bb = Bs + cur * 2048;

        unsigned af[2][4], bf[4][2];
#pragma unroll
        for (int mi = 0; mi < 2; mi++) {
            const int row = wm + mi * 16 + (lane & 15);
            const int p = (lane >> 4) ^ ((row >> 2) & 1);
            unsigned addr = (unsigned)__cvta_generic_to_shared(Ab + row * 32 + p * 16);
            asm volatile("ldmatrix.sync.aligned.m8n8.x4.shared.b16 {%0,%1,%2,%3}, [%4];"
                         : "=r"(af[mi][0]), "=r"(af[mi][1]), "=r"(af[mi][2]), "=r"(af[mi][3])
                         : "r"(addr));
        }
#pragma unroll
        for (int ni = 0; ni < 4; ni++) {
            const int row = wn + ni * 8 + (lane & 7);
            const int p = ((lane >> 3) & 1) ^ ((row >> 2) & 1);
            unsigned addr = (unsigned)__cvta_generic_to_shared(Bb + row * 32 + p * 16);
            asm volatile("ldmatrix.sync.aligned.m8n8.x2.shared.b16 {%0,%1}, [%2];"
                         : "=r"(bf[ni][0]), "=r"(bf[ni][1])
                         : "r"(addr));
        }
#pragma unroll
        for (int mi = 0; mi < 2; mi++)
#pragma unroll
            for (int ni = 0; ni < 4; ni++)
                asm volatile(
                    "mma.sync.aligned.m16n8k32.row.col.f32.e4m3.e4m3.f32 "
                    "{%0,%1,%2,%3}, {%4,%5,%6,%7}, {%8,%9}, {%0,%1,%2,%3};"
                    : "+f"(acc[mi][ni][0]), "+f"(acc[mi][ni][1]),
                      "+f"(acc[mi][ni][2]), "+f"(acc[mi][ni][3])
                    : "r"(af[mi][0]), "r"(af[mi][1]), "r"(af[mi][2]), "r"(af[mi][3]),
                      "r"(bf[ni][0]), "r"(bf[ni][1]));

        if (kt < 49) {
            *(uint4*)&As[(cur ^ 1) * 4096 + sofsA] = ra;
            if (t < 128) *(uint4*)&Bs[(cur ^ 1) * 2048 + sofsB] = rb;
        }
        __syncthreads();
    }

    // epilogue: fq_relu -> bf16 int codes in g_a3
    const float s_in = *ps_in, s_a3 = *ps_a3;
    const float inv_s_a3 = 1.f / s_a3;
    const float scale = s_in * (__uint_as_float(g_absmax[2]) / 7.f);
    const int rg = lane >> 2, cg = (lane & 3) * 2;
#pragma unroll
    for (int mi = 0; mi < 2; mi++) {
#pragma unroll
        for (int ni = 0; ni < 4; ni++) {
            const int row = bm + wm + mi * 16 + rg;
            const int col = bn + wn + ni * 8 + cg;
#pragma unroll
            for (int h = 0; h < 2; h++) {
                const float y0 = acc[mi][ni][h * 2 + 0] * scale;
                const float y1 = acc[mi][ni][h * 2 + 1] * scale;
                const float m0 = (y0 > 0.f) ? fminf(rintf(y0 * inv_s_a3), 15.f) : 0.f;
                const float m1 = (y1 > 0.f) ? fminf(rintf(y1 * inv_s_a3), 15.f) : 0.f;
                __nv_bfloat162 v;
                v.x = __float2bfloat16(m0);
                v.y = __float2bfloat16(m1);
                *(__nv_bfloat162*)&g_a3[(size_t)(row + h * 8) * 4096 + col] = v;
            }
        }
    }
}

// ---------------- fc2: [1024,4096] x [10,4096]^T, 2 images/block ----------------
__global__ __launch_bounds__(256) void fc2_kernel(const float* __restrict__ ps_a3,
                                                  float* __restrict__ out) {
    const int b0 = blockIdx.x * 2;
    const int t = threadIdx.x;
    const int lane = t & 31, warp = t >> 5;
    const float s_a3 = *ps_a3;
    const float swl2 = __uint_as_float(g_absmax[3]) / 7.f;

    const uint4* a4_0 = (const uint4*)(g_a3 + (size_t)b0 * 4096);
    const uint4* a4_1 = (const uint4*)(g_a3 + (size_t)(b0 + 1) * 4096);
    const uint4* w4 = (const uint4*)g_qwl2;

    float part[2][10];
#pragma unroll
    for (int j = 0; j < 10; j++) { part[0][j] = 0.f; part[1][j] = 0.f; }

    for (int k = t; k < 512; k += 256) {
        const uint4 av0 = a4_0[k], av1 = a4_1[k];
        const __nv_bfloat162* ah0 = (const __nv_bfloat162*)&av0;
        const __nv_bfloat162* ah1 = (const __nv_bfloat162*)&av1;
        float2 af0[4], af1[4];
#pragma unroll
        for (int q = 0; q < 4; q++) {
            af0[q] = __bfloat1622float2(ah0[q]);
            af1[q] = __bfloat1622float2(ah1[q]);
        }
#pragma unroll
        for (int j = 0; j < 10; j++) {
            const uint4 wv = w4[j * 512 + k];
            const __nv_bfloat162* wh = (const __nv_bfloat162*)&wv;
#pragma unroll
            for (int q = 0; q < 4; q++) {
                const float2 wf = __bfloat1622float2(wh[q]);
                part[0][j] += af0[q].x * wf.x + af0[q].y * wf.y;
                part[1][j] += af1[q].x * wf.x + af1[q].y * wf.y;
            }
        }
    }
#pragma unroll
    for (int im = 0; im < 2; im++)
#pragma unroll
        for (int j = 0; j < 10; j++)
#pragma unroll
            for (int o = 16; o > 0; o >>= 1)
                part[im][j] += __shfl_xor_sync(0xffffffffu, part[im][j], o);

    __shared__ float red[8][2][10];
    if (lane == 0)
#pragma unroll
        for (int im = 0; im < 2; im++)
#pragma unroll
            for (int j = 0; j < 10; j++) red[warp][im][j] = part[im][j];
    __syncthreads();
    if (t < 20) {
        const int im = t / 10, j = t % 10;
        float s = 0.f;
#pragma unroll
        for (int w = 0; w < 8; w++) s += red[w][im][j];
        out[(b0 + im) * 10 + j] = s * s_a3 * swl2;
    }
}

// ---------------- launch ----------------
extern "C" void kernel_launch(void* const* d_in, const int* in_sizes, int n_in,
                              void* d_out, int out_size) {
    const float* x    = (const float*)d_in[0];
    const float* w1   = (const float*)d_in[1];
    const float* w2   = (const float*)d_in[2];
    const float* wl1  = (const float*)d_in[3];
    const float* wl2  = (const float*)d_in[4];
    const float* s_in = (const float*)d_in[5];
    const float* s_a1 = (const float*)d_in[6];
    const float* s_a2 = (const float*)d_in[7];
    const float* s_a3 = (const float*)d_in[8];
    float* out = (float*)d_out;

    prep1_kernel<<<899, 256>>>((const float4*)wl1, (const float4*)w1,
                               (const float4*)w2, (const float4*)wl2);
    prep2_kernel<<<1848, 256>>>((const float4*)wl1, w2, wl2);
    conv_fused_kernel<<<1024, 256>>>(x, w1, s_in, s_a1, s_a2);
    fc1_kernel<<<dim3(64, 8), 256>>>(s_in, s_a3);
    fc2_kernel<<<512, 256>>>(s_a3, out);
}

// round 15
// speedup vs baseline: 1.1213x; 1.1213x over previous
#include <cuda_runtime.h>
#include <cuda_bf16.h>
#include <cuda_fp8.h>
#include <cstdint>

static constexpr int KP = 1664;    // K padded stride (fc1 iterates only 1600)

// ---------------- scratch (device globals; no allocation) ----------------
// g_absmax is zero-initialized at module load and ONLY written via atomicMax
// with deterministic values -> idempotent across graph replays.
__device__ unsigned g_absmax[4];                                   // w1,w2,wl1,wl2 abs-max bits
__device__ __align__(256) unsigned char g_qwl1f8[4096 * KP];       // wl1 int codes, e4m3, padded K
__device__ __align__(256) __nv_bfloat16 g_qw2p[4 * 64 * 88];       // w2 codes, padded [c][oc][88]
__device__ __align__(256) __nv_bfloat16 g_qwl2[10 * 4096];         // wl2 int codes, bf16
__device__ __align__(256) unsigned char g_a2f8[1024 * KP];         // conv2 out codes, e4m3, padded K
__device__ __align__(256) __nv_bfloat16 g_a3[1024 * 4096];         // fc1 out codes 0..15
__device__ short g_srcIdx[128 * 80];                               // conv2 im2col gather index
__device__ short g_dstIdx[128 * 80];                               // conv2 im2col smem dest

// ---------------- helpers ----------------
__device__ __forceinline__ void warp_max_atomic(float m, int slot) {
#pragma unroll
    for (int o = 16; o > 0; o >>= 1)
        m = fmaxf(m, __shfl_xor_sync(0xffffffffu, m, o));
    if ((threadIdx.x & 31) == 0)
        atomicMax(&g_absmax[slot], __float_as_uint(m));
}

__device__ __forceinline__ float f4max(float4 v) {
    return fmaxf(fmaxf(fabsf(v.x), fabsf(v.y)), fmaxf(fabsf(v.z), fabsf(v.w)));
}

__device__ __forceinline__ float qclip7(float v, float inv_s) {
    float k = rintf(v * inv_s);
    return fminf(fmaxf(k, -7.f), 7.f);
}

__device__ __forceinline__ unsigned short cvt_e4m3x2(float lo, float hi) {
    unsigned short r;
    asm("cvt.rn.satfinite.e4m3x2.f32 %0, %1, %2;" : "=h"(r) : "f"(hi), "f"(lo));
    return r;
}

#define CP_ASYNC16(dst, src) \
    asm volatile("cp.async.cg.shared.global [%0], [%1], 16;" :: "r"(dst), "l"(src))
#define CP_COMMIT() asm volatile("cp.async.commit_group;" ::: "memory")

// ---------------- prep1: all absmax reductions + im2col tables (one launch) ---------------
__global__ void prep1_kernel(const float4* __restrict__ wl1,
                             const float4* __restrict__ w1,
                             const float4* __restrict__ w2,
                             const float4* __restrict__ wl2) {
    const int t = threadIdx.x;
    const unsigned bid = blockIdx.x;
    if (bid < 800) {                         // wl1: 1638400 float4, 8 loads/thread
        const int base = bid * 256 + t;
        const int stride = 800 * 256;
        float4 v[8];
#pragma unroll
        for (int j = 0; j < 8; j++) v[j] = wl1[base + j * stride];
        float m = 0.f;
#pragma unroll
        for (int j = 0; j < 8; j++) m = fmaxf(m, f4max(v[j]));
        warp_max_atomic(m, 2);
    } else if (bid < 859) {
        const int sb = bid - 800;
        float m = 0.f;
        if (sb == 0) {                       // w1: 72 float4
            if (t < 72) m = f4max(w1[t]);
            warp_max_atomic(m, 0);
        } else if (sb <= 18) {               // w2: 4608 float4
            const int i = (sb - 1) * 256 + t;
            if (i < 4608) m = f4max(w2[i]);
            warp_max_atomic(m, 1);
        } else {                             // wl2: 10240 float4
            const int i = (sb - 19) * 256 + t;
            if (i < 10240) m = f4max(wl2[i]);
            warp_max_atomic(m, 3);
        }
    } else {                                 // im2col tables: 10240 entries
        const int idx = (bid - 859) * 256 + t;
        if (idx < 128 * 80) {
            const int r = idx / 80, col = idx % 80;
            short s = -1;
            if (r < 121 && col < 72) {
                const int icl = col / 9, kk = col % 9;
                const int ky = kk / 3, kx = kk % 3;
                const int oy = r / 11, ox = r % 11;
                s = (short)(icl * 169 + (oy + ky) * 13 + ox + kx);
            }
            g_srcIdx[idx] = s;
            g_dstIdx[idx] = (short)(r * 88 + col);
        }
    }
}

// ---------------- prep2: all weight quantization (one launch) ----------------
__global__ void prep2_kernel(const float4* __restrict__ wl1,
                             const float* __restrict__ w2,
                             const float* __restrict__ wl2) {
    const int t = threadIdx.x;
    const unsigned bid = blockIdx.x;
    if (bid < 1600) {
        const float inv_s = 7.f / __uint_as_float(g_absmax[2]);
        const int i = bid * 256 + t;          // 0 .. 409599, 16 elems/thread
        unsigned short h[8];
#pragma unroll
        for (int q = 0; q < 4; q++) {
            float4 a = wl1[4 * i + q];
            h[2 * q + 0] = cvt_e4m3x2(qclip7(a.x, inv_s), qclip7(a.y, inv_s));
            h[2 * q + 1] = cvt_e4m3x2(qclip7(a.z, inv_s), qclip7(a.w, inv_s));
        }
        const int row = i / 100, c16 = i % 100;    // 1600/16 = 100 granules per row
        *(uint4*)&g_qwl1f8[(size_t)row * KP + c16 * 16] = *(const uint4*)h;
    } else if (bid < 1688) {                  // g_qw2p: 22528 entries
        const int idx = (bid - 1600) * 256 + t;
        if (idx < 22528) {
            const int c = idx / 5632, rem = idx % 5632;
            const int oc = rem / 88, col = rem % 88;
            float v = 0.f;
            if (col < 72) {
                const float inv_s = 7.f / __uint_as_float(g_absmax[1]);
                v = qclip7(w2[oc * 288 + c * 72 + col], inv_s);
            }
            g_qw2p[idx] = __float2bfloat16(v);
        }
    } else {                                  // wl2: 40960 entries
        const int i = (bid - 1688) * 256 + t;
        const float inv_s = 7.f / __uint_as_float(g_absmax[3]);
        g_qwl2[i] = __float2bfloat16(qclip7(wl2[i], inv_s));
    }
}

// ---------------- fused conv: conv1 -> pool -> fq -> conv2 (MMA) -> pool -> fq ----------------
static constexpr int C2_RS = 88;
static constexpr int SI_OFF = 0;
static constexpr int SA_OFF = 10880;
static constexpr int SB_OFF = 33408;
static constexpr int SO_OFF = 0;

__global__ __launch_bounds__(256) void conv_fused_kernel(const float* __restrict__ x,
                                                         const float* __restrict__ w1,
                                                         const float* __restrict__ ps_in,
                                                         const float* __restrict__ ps_a1,
                                                         const float* __restrict__ ps_a2) {
    __shared__ __align__(16) unsigned char smraw[44672];
    __nv_bfloat16* si = (__nv_bfloat16*)(smraw + SI_OFF);
    __nv_bfloat16* sA = (__nv_bfloat16*)(smraw + SA_OFF);
    __nv_bfloat16* sB = (__nv_bfloat16*)(smraw + SB_OFF);

    const int b = blockIdx.x;
    const int t = threadIdx.x;
    const int lane = t & 31, warp = t >> 5;
    const int wm = (warp >> 1) * 32;
    const int wn = (warp & 1) * 32;

    const float s_in = *ps_in;
    const float inv_s_in = 1.f / s_in;

    // ===== conv1 phase =====
    {
        float* sx = (float*)(smraw + SA_OFF);
        float* sw = (float*)(smraw + SA_OFF + 3200);
        const float s_a1 = *ps_a1;
        const float inv_s_a1 = 1.f / s_a1;
        const float inv_w1 = 7.f / __uint_as_float(g_absmax[0]);

        const float* xb = x + b * 784;
        for (int i = t; i < 784; i += 256) {
            float q = rintf(xb[i] * inv_s_in);
            sx[i] = fminf(fmaxf(q, -8.f), 7.f);
        }
        for (int i = t; i < 288; i += 256)
            sw[i] = qclip7(w1[i], inv_w1);
        __syncthreads();

        const float oscale = s_in * (__uint_as_float(g_absmax[0]) / 7.f);
        for (int o = t; o < 32 * 169; o += 256) {
            const int c = o / 169;
            const int r = o % 169;
            const int pi = r / 13, pj = r % 13;
            const float* wk = sw + c * 9;
            float m = 0.f;
#pragma unroll
            for (int dy = 0; dy < 2; dy++) {
#pragma unroll
                for (int dx = 0; dx < 2; dx++) {
                    const int r0 = 2 * pi + dy, c0 = 2 * pj + dx;
                    float acc = 0.f;
#pragma unroll
                    for (int ky = 0; ky < 3; ky++)
#pragma unroll
                        for (int kx = 0; kx < 3; kx++)
                            acc += sx[(r0 + ky) * 28 + (c0 + kx)] * wk[ky * 3 + kx];
                    const float y = acc * oscale;
                    const float mm = (y > 0.f) ? fminf(rintf(y * inv_s_a1), 15.f) : 0.f;
                    m = fmaxf(m, mm);
                }
            }
            float k = rintf(m * s_a1 * inv_s_in);
            k = fminf(fmaxf(k, -8.f), 7.f);
            si[o] = __float2bfloat16(k);
        }
    }

    // ===== conv2 phase =====
    float acc[2][4][4];
#pragma unroll
    for (int mi = 0; mi < 2; mi++)
#pragma unroll
        for (int ni = 0; ni < 4; ni++)
#pragma unroll
            for (int q = 0; q < 4; q++) acc[mi][ni][q] = 0.f;

    const __nv_bfloat16 zero = __float2bfloat16(0.f);

    for (int c = 0; c < 4; ++c) {
        __syncthreads();
        {
            const int base = c * 1352;
#pragma unroll 8
            for (int i = 0; i < 40; i++) {
                const int idx = t + 256 * i;
                const short s = g_srcIdx[idx];
                const short d = g_dstIdx[idx];
                sA[d] = (s >= 0) ? si[base + s] : zero;
            }
        }
        {
            const uint4* src = (const uint4*)(g_qw2p + c * 5632);
            uint4* dst = (uint4*)sB;
#pragma unroll
            for (int i = t; i < 704; i += 256) dst[i] = src[i];
        }
        __syncthreads();

#pragma unroll
        for (int ks = 0; ks < 5; ++ks) {
            const int k0 = ks * 16;
            unsigned af[2][4], bf[4][2];
#pragma unroll
            for (int mi = 0; mi < 2; mi++) {
                const int row = wm + mi * 16 + (lane & 15);
                const int g = (k0 >> 3) + (lane >> 4);
                unsigned addr = (unsigned)__cvta_generic_to_shared(sA + row * C2_RS + g * 8);
                asm volatile("ldmatrix.sync.aligned.m8n8.x4.shared.b16 {%0,%1,%2,%3}, [%4];"
                             : "=r"(af[mi][0]), "=r"(af[mi][1]), "=r"(af[mi][2]), "=r"(af[mi][3])
                             : "r"(addr));
            }
#pragma unroll
            for (int ni = 0; ni < 4; ni++) {
                const int row = wn + ni * 8 + (lane & 7);
                const int g = (k0 >> 3) + ((lane >> 3) & 1);
                unsigned addr = (unsigned)__cvta_generic_to_shared(sB + row * C2_RS + g * 8);
                asm volatile("ldmatrix.sync.aligned.m8n8.x2.shared.b16 {%0,%1}, [%2];"
                             : "=r"(bf[ni][0]), "=r"(bf[ni][1])
                             : "r"(addr));
            }
#pragma unroll
            for (int mi = 0; mi < 2; mi++)
#pragma unroll
                for (int ni = 0; ni < 4; ni++)
                    asm volatile(
                        "mma.sync.aligned.m16n8k16.row.col.f32.bf16.bf16.f32 "
                        "{%0,%1,%2,%3}, {%4,%5,%6,%7}, {%8,%9}, {%0,%1,%2,%3};"
                        : "+f"(acc[mi][ni][0]), "+f"(acc[mi][ni][1]),
                          "+f"(acc[mi][ni][2]), "+f"(acc[mi][ni][3])
                        : "r"(af[mi][0]), "r"(af[mi][1]), "r"(af[mi][2]), "r"(af[mi][3]),
                          "r"(bf[ni][0]), "r"(bf[ni][1]));
        }
    }
    __syncthreads();

    float* sO = (float*)(smraw + SO_OFF);
    {
        const int rg = lane >> 2, cg = (lane & 3) * 2;
#pragma unroll
        for (int mi = 0; mi < 2; mi++)
#pragma unroll
            for (int ni = 0; ni < 4; ni++) {
                const int r0 = wm + mi * 16 + rg;
                const int cc = wn + ni * 8 + cg;
                *(float2*)&sO[r0 * 64 + cc] = make_float2(acc[mi][ni][0], acc[mi][ni][1]);
                *(float2*)&sO[(r0 + 8) * 64 + cc] = make_float2(acc[mi][ni][2], acc[mi][ni][3]);
            }
    }
    __syncthreads();

    const float s_a2 = *ps_a2;
    const float inv_s_a2 = 1.f / s_a2;
    const float osc = s_in * (__uint_as_float(g_absmax[1]) / 7.f);
    if (t < 200) {
        const int sp = t % 25, g = t / 25;
        const int ph = sp / 5, pw = sp % 5;
#pragma unroll
        for (int j = 0; j < 8; j++) {
            const int oc = g * 8 + j;
            float m = 0.f;
#pragma unroll
            for (int dy = 0; dy < 2; dy++)
#pragma unroll
                for (int dx = 0; dx < 2; dx++) {
                    const int pos = (2 * ph + dy) * 11 + (2 * pw + dx);
                    const float y = sO[pos * 64 + oc] * osc;
                    const float mm = (y > 0.f) ? fminf(rintf(y * inv_s_a2), 15.f) : 0.f;
                    m = fmaxf(m, mm);
                }
            float k = rintf(m * s_a2 * inv_s_in);
            k = fminf(fmaxf(k, -8.f), 7.f);
            g_a2f8[(size_t)b * KP + oc * 25 + ph * 5 + pw] =
                __nv_cvt_float_to_fp8(k, __NV_SATFINITE, __NV_E4M3);
        }
    }
}

// ---------------- fc1: FP8 e4m3 m16n8k32, tile 128x128, k-tile 64, cp.async ----------------
// Swizzle: 64B rows, 4 granules of 16B; p = g ^ ((row>>1)&3) -> conflict-free for all
// ldmatrix phases (even rows: half-phase 0, 4 distinct granules; odd rows: half-phase 1).
__global__ __launch_bounds__(256, 2) void fc1_kernel(const float* __restrict__ ps_in,
                                                     const float* __restrict__ ps_a3) {
    __shared__ __align__(16) unsigned char As[2 * 128 * 64];   // 16 KB
    __shared__ __align__(16) unsigned char Bs[2 * 128 * 64];   // 16 KB
    const int t = threadIdx.x;
    const int lane = t & 31, warp = t >> 5;
    const int wm = (warp >> 2) * 64;    // 2 warps in M (64 rows each)
    const int wn = (warp & 3) * 32;     // 4 warps in N (32 cols each)
    const int bm = blockIdx.y * 128, bn = blockIdx.x * 128;

    const unsigned char* Ag = g_a2f8;
    const unsigned char* Bg = g_qwl1f8;

    // loader: thread t -> row t>>1, granules {(t&1)*2, (t&1)*2+1}
    const int lr = t >> 1;
    const int kgb = (t & 1) * 2;
    const int sw_lr = (lr >> 1) & 3;
    const uint32_t dA0 = (uint32_t)__cvta_generic_to_shared(As) + lr * 64 + ((kgb ^ sw_lr)) * 16;
    const uint32_t dA1 = (uint32_t)__cvta_generic_to_shared(As) + lr * 64 + (((kgb + 1) ^ sw_lr)) * 16;
    const uint32_t dB0 = (uint32_t)__cvta_generic_to_shared(Bs) + lr * 64 + ((kgb ^ sw_lr)) * 16;
    const uint32_t dB1 = (uint32_t)__cvta_generic_to_shared(Bs) + lr * 64 + (((kgb + 1) ^ sw_lr)) * 16;
    const unsigned char* srcA = Ag + (size_t)(bm + lr) * KP + kgb * 16;
    const unsigned char* srcB = Bg + (size_t)(bn + lr) * KP + kgb * 16;

    float acc[4][4][4];
#pragma unroll
    for (int mi = 0; mi < 4; mi++)
#pragma unroll
        for (int ni = 0; ni < 4; ni++)
#pragma unroll
            for (int q = 0; q < 4; q++) acc[mi][ni][q] = 0.f;

    // prologue: fill buffer 0 (k-tile 0)
    CP_ASYNC16(dA0, srcA);
    CP_ASYNC16(dA1, srcA + 16);
    CP_ASYNC16(dB0, srcB);
    CP_ASYNC16(dB1, srcB + 16);
    CP_COMMIT();

    for (int kt = 0; kt < 25; ++kt) {
        const int cur = kt & 1;
        if (kt < 24) {
            const int nb = (cur ^ 1) * 8192;
            const int k0 = (kt + 1) * 64;
            CP_ASYNC16(dA0 + nb, srcA + k0);
            CP_ASYNC16(dA1 + nb, srcA + k0 + 16);
            CP_ASYNC16(dB0 + nb, srcB + k0);
            CP_ASYNC16(dB1 + nb, srcB + k0 + 16);
            CP_COMMIT();
            asm volatile("cp.async.wait_group 1;" ::: "memory");
        } else {
            asm volatile("cp.async.wait_group 0;" ::: "memory");
        }
        __syncthreads();

        const unsigned char* Ab = As + cur * 8192;
        const unsigned char* Bb = Bs + cur * 8192;
#pragma unroll
        for (int ks = 0; ks < 2; ++ks) {
            unsigned af[4][4], bf[4][2];
#pragma unroll
            for (int mi = 0; mi < 4; mi++) {
                const int row = wm + mi * 16 + (lane & 15);
                const int g = ks * 2 + (lane >> 4);
                const int p = g ^ ((row >> 1) & 3);
                unsigned addr = (unsigned)__cvta_generic_to_shared(Ab + row * 64 + p * 16);
                asm volatile("ldmatrix.sync.aligned.m8n8.x4.shared.b16 {%0,%1,%2,%3}, [%4];"
                             : "=r"(af[mi][0]), "=r"(af[mi][1]), "=r"(af[mi][2]), "=r"(af[mi][3])
                             : "r"(addr));
            }
#pragma unroll
            for (int np = 0; np < 2; np++) {
                const int row = wn + np * 16 + ((lane >> 4) & 1) * 8 + (lane & 7);
                const int g = ks * 2 + ((lane >> 3) & 1);
                const int p = g ^ ((row >> 1) & 3);
                unsigned addr = (unsigned)__cvta_generic_to_shared(Bb + row * 64 + p * 16);
                asm volatile("ldmatrix.sync.aligned.m8n8.x4.shared.b16 {%0,%1,%2,%3}, [%4];"
                             : "=r"(bf[2 * np][0]), "=r"(bf[2 * np][1]),
                               "=r"(bf[2 * np + 1][0]), "=r"(bf[2 * np + 1][1])
                             : "r"(addr));
            }
#pragma unroll
            for (int mi = 0; mi < 4; mi++)
#pragma unroll
                for (int ni = 0; ni < 4; ni++)
                    asm volatile(
                        "mma.sync.aligned.m16n8k32.row.col.f32.e4m3.e4m3.f32 "
                        "{%0,%1,%2,%3}, {%4,%5,%6,%7}, {%8,%9}, {%0,%1,%2,%3};"
                        : "+f"(acc[mi][ni][0]), "+f"(acc[mi][ni][1]),
                          "+f"(acc[mi][ni][2]), "+f"(acc[mi][ni][3])
                        : "r"(af[mi][0]), "r"(af[mi][1]), "r"(af[mi][2]), "r"(af[mi][3]),
                          "r"(bf[ni][0]), "r"(bf[ni][1]));
        }
        __syncthreads();    // all warps done reading before next issue overwrites
    }

    // epilogue: fq_relu -> bf16 int codes in g_a3
    const float s_in = *ps_in, s_a3 = *ps_a3;
    const float inv_s_a3 = 1.f / s_a3;
    const float scale = s_in * (__uint_as_float(g_absmax[2]) / 7.f);
    const int rg = lane >> 2, cg = (lane & 3) * 2;
#pragma unroll
    for (int mi = 0; mi < 4; mi++) {
#pragma unroll
        for (int ni = 0; ni < 4; ni++) {
            const int row = bm + wm + mi * 16 + rg;
            const int col = bn + wn + ni * 8 + cg;
#pragma unroll
            for (int h = 0; h < 2; h++) {
                const float y0 = acc[mi][ni][h * 2 + 0] * scale;
                const float y1 = acc[mi][ni][h * 2 + 1] * scale;
                const float m0 = (y0 > 0.f) ? fminf(rintf(y0 * inv_s_a3), 15.f) : 0.f;
                const float m1 = (y1 > 0.f) ? fminf(rintf(y1 * inv_s_a3), 15.f) : 0.f;
                __nv_bfloat162 v;
                v.x = __float2bfloat16(m0);
                v.y = __float2bfloat16(m1);
                *(__nv_bfloat162*)&g_a3[(size_t)(row + h * 8) * 4096 + col] = v;
            }
        }
    }
}

// ---------------- fc2: [1024,4096] x [10,4096]^T, 2 images/block ----------------
__global__ __launch_bounds__(256) void fc2_kernel(const float* __restrict__ ps_a3,
                                                  float* __restrict__ out) {
    const int b0 = blockIdx.x * 2;
    const int t = threadIdx.x;
    const int lane = t & 31, warp = t >> 5;
    const float s_a3 = *ps_a3;
    const float swl2 = __uint_as_float(g_absmax[3]) / 7.f;

    const uint4* a4_0 = (const uint4*)(g_a3 + (size_t)b0 * 4096);
    const uint4* a4_1 = (const uint4*)(g_a3 + (size_t)(b0 + 1) * 4096);
    const uint4* w4 = (const uint4*)g_qwl2;

    float part[2][10];
#pragma unroll
    for (int j = 0; j < 10; j++) { part[0][j] = 0.f; part[1][j] = 0.f; }

    for (int k = t; k < 512; k += 256) {
        const uint4 av0 = a4_0[k], av1 = a4_1[k];
        const __nv_bfloat162* ah0 = (const __nv_bfloat162*)&av0;
        const __nv_bfloat162* ah1 = (const __nv_bfloat162*)&av1;
        float2 af0[4], af1[4];
#pragma unroll
        for (int q = 0; q < 4; q++) {
            af0[q] = __bfloat1622float2(ah0[q]);
            af1[q] = __bfloat1622float2(ah1[q]);
        }
#pragma unroll
        for (int j = 0; j < 10; j++) {
            const uint4 wv = w4[j * 512 + k];
            const __nv_bfloat162* wh = (const __nv_bfloat162*)&wv;
#pragma unroll
            for (int q = 0; q < 4; q++) {
                const float2 wf = __bfloat1622float2(wh[q]);
                part[0][j] += af0[q].x * wf.x + af0[q].y * wf.y;
                part[1][j] += af1[q].x * wf.x + af1[q].y * wf.y;
            }
        }
    }
#pragma unroll
    for (int im = 0; im < 2; im++)
#pragma unroll
        for (int j = 0; j < 10; j++)
#pragma unroll
            for (int o = 16; o > 0; o >>= 1)
                part[im][j] += __shfl_xor_sync(0xffffffffu, part[im][j], o);

    __shared__ float red[8][2][10];
    if (lane == 0)
#pragma unroll
        for (int im = 0; im < 2; im++)
#pragma unroll
            for (int j = 0; j < 10; j++) red[warp][im][j] = part[im][j];
    __syncthreads();
    if (t < 20) {
        const int im = t / 10, j = t % 10;
        float s = 0.f;
#pragma unroll
        for (int w = 0; w < 8; w++) s += red[w][im][j];
        out[(b0 + im) * 10 + j] = s * s_a3 * swl2;
    }
}

// ---------------- launch ----------------
extern "C" void kernel_launch(void* const* d_in, const int* in_sizes, int n_in,
                              void* d_out, int out_size) {
    const float* x    = (const float*)d_in[0];
    const float* w1   = (const float*)d_in[1];
    const float* w2   = (const float*)d_in[2];
    const float* wl1  = (const float*)d_in[3];
    const float* wl2  = (const float*)d_in[4];
    const float* s_in = (const float*)d_in[5];
    const float* s_a1 = (const float*)d_in[6];
    const float* s_a2 = (const float*)d_in[7];
    const float* s_a3 = (const float*)d_in[8];
    float* out = (float*)d_out;

    prep1_kernel<<<899, 256>>>((const float4*)wl1, (const float4*)w1,
                               (const float4*)w2, (const float4*)wl2);
    prep2_kernel<<<1848, 256>>>((const float4*)wl1, w2, wl2);
    conv_fused_kernel<<<1024, 256>>>(x, w1, s_in, s_a1, s_a2);
    fc1_kernel<<<dim3(32, 8), 256>>>(s_in, s_a3);
    fc2_kernel<<<512, 256>>>(s_a3, out);
}